// round 1
// baseline (speedup 1.0000x reference)
#include <cuda_runtime.h>
#include <cstdint>

// Problem constants
#define NIN    1024          // inner (reduced) dim
#define NOUT   4096          // output columns
#define NROWS  64            // BATCH*FEAT = 2*32
#define TM     32            // m-columns per block
#define NGRP   32            // NIN/32 bit-groups
#define CSTRIDE 36           // padded smem stride (words) for colT: conflict-free LDS.128

__global__ __launch_bounds__(256)
void pool_clique_kernel(const float* __restrict__ x,
                        const float* __restrict__ B,
                        float* __restrict__ out)
{
    __shared__ unsigned colT[TM * CSTRIDE];   // colT[c*CSTRIDE + g] = 32-bit occupancy of column c, n-group g

    const int t    = threadIdx.x;
    const int lane = t & 31;
    const int w    = t >> 5;            // warp id 0..7
    const int m0   = blockIdx.x * TM;   // column tile base

    // ---------------- Phase 1: build per-column bitmaps from B ----------------
    // Warp w handles n-groups g = 4w .. 4w+3 (each group = 32 consecutive n).
    // Lane mapping inside a group: r0 = lane>>3 selects row-phase 0..3,
    // cq = lane&7 selects a 4-column chunk. One LDG.128 covers 4 rows x warp.
    {
        const int r0 = lane >> 3;
        const int cq = lane & 7;
        const unsigned mm = 0x01010101u << cq;   // the 4 lanes sharing this column chunk
        #pragma unroll
        for (int gi = 0; gi < 4; gi++) {
            const int g  = w * 4 + gi;
            const int n0 = g * 32;
            unsigned p0 = 0, p1 = 0, p2 = 0, p3 = 0;
            const float4* bp = reinterpret_cast<const float4*>(
                B + (size_t)(n0 + r0) * NOUT + m0 + cq * 4);
            #pragma unroll
            for (int i = 0; i < 8; i++) {
                float4 v = __ldg(bp);
                bp += NOUT;                       // advance 4 rows (NOUT float4s = 4*NOUT floats)
                const unsigned bit = 1u << (i * 4 + r0);
                if (v.x != 0.0f) p0 |= bit;
                if (v.y != 0.0f) p1 |= bit;
                if (v.z != 0.0f) p2 |= bit;
                if (v.w != 0.0f) p3 |= bit;
            }
            // OR across the 4 row-phase lanes -> full 32-bit group bitmap per column
            p0 = __reduce_or_sync(mm, p0);
            p1 = __reduce_or_sync(mm, p1);
            p2 = __reduce_or_sync(mm, p2);
            p3 = __reduce_or_sync(mm, p3);
            if (r0 == 0) {
                const int c = cq * 4;
                colT[(c + 0) * CSTRIDE + g] = p0;
                colT[(c + 1) * CSTRIDE + g] = p1;
                colT[(c + 2) * CSTRIDE + g] = p2;
                colT[(c + 3) * CSTRIDE + g] = p3;
            }
        }
    }
    __syncthreads();

    // ---------------- Phase 2: sparse gather-max ----------------
    // Thread owns column m = lane, rows rg*8 .. rg*8+7 (rg = warp id).
    const int m  = lane;
    const int rg = w;

    unsigned cm[NGRP];
    #pragma unroll
    for (int q = 0; q < 8; q++) {
        uint4 v = *reinterpret_cast<const uint4*>(&colT[m * CSTRIDE + q * 4]);
        cm[q * 4 + 0] = v.x;
        cm[q * 4 + 1] = v.y;
        cm[q * 4 + 2] = v.z;
        cm[q * 4 + 3] = v.w;
    }

    // all-ones check: if every B[n, m] == 1 the zero does NOT participate in the max
    unsigned andall = 0xFFFFFFFFu;
    #pragma unroll
    for (int g = 0; g < NGRP; g++) andall &= cm[g];

    float acc[8];
    #pragma unroll
    for (int k = 0; k < 8; k++) acc[k] = -__int_as_float(0x7f800000);  // -inf

    const float* xp = x + (size_t)rg * 8 * NIN;
    #pragma unroll
    for (int g = 0; g < NGRP; g++) {
        unsigned c = cm[g];
        while (c) {
            const int b = __ffs(c) - 1;
            c &= c - 1;
            const float* xq = xp + g * 32 + b;
            #pragma unroll
            for (int k = 0; k < 8; k++)
                acc[k] = fmaxf(acc[k], __ldg(xq + (size_t)k * NIN));
        }
    }

    if (andall != 0xFFFFFFFFu) {
        #pragma unroll
        for (int k = 0; k < 8; k++) acc[k] = fmaxf(acc[k], 0.0f);
    }

    float* op = out + (size_t)(rg * 8) * NOUT + m0 + m;
    #pragma unroll
    for (int k = 0; k < 8; k++) op[(size_t)k * NOUT] = acc[k];
}

extern "C" void kernel_launch(void* const* d_in, const int* in_sizes, int n_in,
                              void* d_out, int out_size)
{
    const float* x = (const float*)d_in[0];   // (2, 32, 1024) f32
    const float* B = (const float*)d_in[1];   // (1024, 4096) f32, 0/1
    float* out     = (float*)d_out;           // (2, 32, 4096) f32
    (void)in_sizes; (void)n_in; (void)out_size;

    pool_clique_kernel<<<NOUT / TM, 256>>>(x, B, out);
}

// round 3
// speedup vs baseline: 1.3020x; 1.3020x over previous
#include <cuda_runtime.h>
#include <cstdint>

#define NIN   1024
#define NOUT  4096
#define NROWS 64           // BATCH*FEAT

// Bitmap scratch: bm[g*NOUT + col], g = n-group (32 n per group), 32 groups.
__device__ unsigned g_bm[32 * NOUT];   // 512 KB

// ---------------------------------------------------------------------------
// Kernel 1: build per-column occupancy bitmaps from B (exactly 0.0f / 1.0f).
// grid = (NOUT/32, NIN/256) = (128, 4), 256 threads (8 warps).
// Warp w handles n-group g = by*8 + w (32 rows of B). Lane mapping:
// r0 = lane>>3 row phase (4 rows interleaved), cq = lane&7 column quartet.
// 8 LDG.128 per lane (batched -> high MLP), bit extracted from fp32 exponent.
// ---------------------------------------------------------------------------
__global__ __launch_bounds__(256)
void k_bitmap(const float* __restrict__ B)
{
    const int lane = threadIdx.x & 31;
    const int w    = threadIdx.x >> 5;
    const int m0   = blockIdx.x * 32;
    const int g    = blockIdx.y * 8 + w;
    const int n0   = g * 32;
    const int r0   = lane >> 3;
    const int cq   = lane & 7;

    const float4* bp = reinterpret_cast<const float4*>(
        B + (size_t)(n0 + r0) * NOUT + m0 + cq * 4);

    unsigned p0 = 0, p1 = 0, p2 = 0, p3 = 0;
    #pragma unroll
    for (int i = 0; i < 8; i++) {
        float4 v = __ldg(bp + (size_t)i * NOUT);   // advance 4 rows per step
        const unsigned pos = i * 4 + r0;
        p0 |= ((__float_as_uint(v.x) >> 23) & 1u) << pos;
        p1 |= ((__float_as_uint(v.y) >> 23) & 1u) << pos;
        p2 |= ((__float_as_uint(v.z) >> 23) & 1u) << pos;
        p3 |= ((__float_as_uint(v.w) >> 23) & 1u) << pos;
    }

    // OR across the 4 row-phase lanes sharing this column quartet
    const unsigned mm = 0x01010101u << cq;
    p0 = __reduce_or_sync(mm, p0);
    p1 = __reduce_or_sync(mm, p1);
    p2 = __reduce_or_sync(mm, p2);
    p3 = __reduce_or_sync(mm, p3);

    if (r0 == 0) {
        // 4 consecutive columns, same g -> one STG.128
        uint4 v4 = make_uint4(p0, p1, p2, p3);
        *reinterpret_cast<uint4*>(&g_bm[(size_t)g * NOUT + m0 + cq * 4]) = v4;
    }
}

// ---------------------------------------------------------------------------
// Kernel 2: sparse gather-max with x staged in SMEM (no L1 sector waste).
// grid = (NOUT/64, NROWS/8) = (64, 8), 256 threads.
// Thread owns column c = t&63 and row pair rh = t>>6 (rows 2rh, 2rh+1 of the
// 8-row block). Bitmaps padded to stride 33 words -> conflict-free reads.
// ---------------------------------------------------------------------------
__global__ __launch_bounds__(256)
void k_pool(const float* __restrict__ x, float* __restrict__ out)
{
    __shared__ float    xs[8 * NIN];        // 32 KB: 8 rows of x
    __shared__ unsigned bms[64 * 33];       // 8.25 KB: 64 cols x 32 groups

    const int t    = threadIdx.x;
    const int lane = t & 31;
    const int w    = t >> 5;                // warp 0..7
    const int c0   = blockIdx.x * 64;
    const int r0   = blockIdx.y * 8;        // row-block base

    // Stage 8 x-rows: 2048 float4, coalesced
    {
        const float4* xp = reinterpret_cast<const float4*>(x + (size_t)r0 * NIN);
        float4* xs4 = reinterpret_cast<float4*>(xs);
        #pragma unroll
        for (int i = 0; i < 8; i++)
            xs4[t + i * 256] = __ldg(xp + t + i * 256);
    }

    // Stage bitmaps with uint4 loads: warp w loads group g = p*8 + w;
    // lane covers columns 4*lane .. 4*lane+3 of the 64-wide tile (lanes 0..15).
    #pragma unroll
    for (int p = 0; p < 4; p++) {
        const int g = p * 8 + w;
        if (lane < 16) {
            uint4 v = __ldg(reinterpret_cast<const uint4*>(
                &g_bm[(size_t)g * NOUT + c0 + lane * 4]));
            bms[(lane * 4 + 0) * 33 + g] = v.x;
            bms[(lane * 4 + 1) * 33 + g] = v.y;
            bms[(lane * 4 + 2) * 33 + g] = v.z;
            bms[(lane * 4 + 3) * 33 + g] = v.w;
        }
    }
    __syncthreads();

    const int c  = t & 63;
    const int rh = t >> 6;                  // 0..3 -> rows 2rh, 2rh+1
    const float* xr0 = xs + (rh * 2) * NIN;
    const float* xr1 = xr0 + NIN;

    float a0 = -__int_as_float(0x7f800000); // -inf
    float a1 = a0;
    unsigned andall = 0xFFFFFFFFu;

    for (int g = 0; g < 32; g++) {
        unsigned wv = bms[c * 33 + g];
        andall &= wv;
        while (wv) {
            const int b = __ffs(wv) - 1;
            wv &= wv - 1;
            const int n = g * 32 + b;
            a0 = fmaxf(a0, xr0[n]);
            a1 = fmaxf(a1, xr1[n]);
        }
    }

    if (andall != 0xFFFFFFFFu) {            // zero participates unless all-ones col
        a0 = fmaxf(a0, 0.0f);
        a1 = fmaxf(a1, 0.0f);
    }

    const int row = r0 + rh * 2;
    out[(size_t)row * NOUT + c0 + c]       = a0;
    out[(size_t)(row + 1) * NOUT + c0 + c] = a1;
}

// ---------------------------------------------------------------------------
extern "C" void kernel_launch(void* const* d_in, const int* in_sizes, int n_in,
                              void* d_out, int out_size)
{
    const float* x = (const float*)d_in[0];   // (2, 32, 1024) f32
    const float* B = (const float*)d_in[1];   // (1024, 4096) f32, exact 0/1
    float* out     = (float*)d_out;           // (2, 32, 4096) f32
    (void)in_sizes; (void)n_in; (void)out_size;

    k_bitmap<<<dim3(NOUT / 32, NIN / 256), 256>>>(B);
    k_pool  <<<dim3(NOUT / 64, NROWS / 8), 256>>>(x, out);
}